// round 14
// baseline (speedup 1.0000x reference)
#include <cuda_runtime.h>
#include <cuda_fp16.h>
#include <cstdint>

typedef uint32_t u32;

#define NT     256
#define LMN    68
#define NTOT   77
#define XSTRB  176        // xT row bytes (80 n-cols padded, fp16)
#define ASTRB  272        // agg row bytes (128 d-cols padded, fp16)

// state block (per CTA = one graph)
#define XH_OF  0          // xT hi tile  (128 x 176B = 22528)
#define XL_OF  22528      // xT lo tile  (residual precision only)
#define AH_OF  45056      // agg hi tile (80 x 272B = 21760) -- no lo tile needed
#define GSZ    66816
#define O_G    (GSZ)
#define O_BE   (GSZ+512)
#define O_SS   (GSZ+1024)
#define O_SW   (GSZ+1408)
#define SMEM_SZ (GSZ+1792)   // 68608 B -> 3 CTAs/SM

// frag tables: exact mma.m16n8k16 A-fragment layout, fp16 hi/lo split
__device__ uint4 g_af[5*5*2*32];        // adj  [band5][k5][hl2][lane32]
__device__ uint4 g_wf[4*8*8*2*32];      // W^T  [L4][band8][k8][hl2][lane32]

__constant__ int2 c_reg[9] = {
  {0,16},{17,21},{22,26},{27,30},{31,35},{36,41},{42,47},{48,59},{60,67}
};

__device__ __forceinline__ u32 h2pack(float a, float b){ // low16=fp16(a), high16=fp16(b)
  __half2 h = __floats2half2_rn(a, b);
  return *(u32*)&h;
}
__device__ __forceinline__ u32 h2lo(float p, float q, u32 h){
  __half2 hh = *(__half2*)&h;
  return h2pack(p - __half2float(__low2half(hh)), q - __half2float(__high2half(hh)));
}
__device__ __forceinline__ float2 h2unpack(u32 v){
  return __half22float2(*(__half2*)&v);
}
__device__ __forceinline__ void ldm4(u32* r, u32 addr){
  asm volatile("ldmatrix.sync.aligned.m8n8.x4.shared.b16 {%0,%1,%2,%3}, [%4];"
    : "=r"(r[0]),"=r"(r[1]),"=r"(r[2]),"=r"(r[3]) : "r"(addr));
}
__device__ __forceinline__ void mma(float* c, const u32* a, u32 b0, u32 b1){
  asm volatile("mma.sync.aligned.m16n8k16.row.col.f32.f16.f16.f32 "
    "{%0,%1,%2,%3},{%4,%5,%6,%7},{%8,%9},{%0,%1,%2,%3};"
    : "+f"(c[0]),"+f"(c[1]),"+f"(c[2]),"+f"(c[3])
    : "r"(a[0]),"r"(a[1]),"r"(a[2]),"r"(a[3]), "r"(b0),"r"(b1));
}

// ---------------- format kernel: build fp16 hi/lo A-frag tables ----------------
__global__ void __launch_bounds__(256)
format_kernel(const float* __restrict__ adj,
              const float* __restrict__ W0, const float* __restrict__ W1,
              const float* __restrict__ W2, const float* __restrict__ W3)
{
  const int b = blockIdx.x;
  const float* Ws[4] = {W0,W1,W2,W3};
  if (b == 0){
    for (int idx = threadIdx.x; idx < 5*5*32; idx += 256){
      int lane = idx & 31, k = (idx >> 5) % 5, band = idx / 160;
      u32 H[4], L[4];
      #pragma unroll
      for (int j = 0; j < 4; j++){
        int row = band*16 + (lane>>2) + (j&1)*8;
        int cp  = k*16 + (lane&3)*2 + (j>>1)*8;
        float p = (row < NTOT && cp   < NTOT) ? adj[row*NTOT + cp]   : 0.f;
        float q = (row < NTOT && cp+1 < NTOT) ? adj[row*NTOT + cp+1] : 0.f;
        H[j] = h2pack(p,q);
        L[j] = h2lo(p,q,H[j]);
      }
      int base = ((band*5 + k)*2)*32 + lane;
      g_af[base]      = make_uint4(H[0],H[1],H[2],H[3]);
      g_af[base + 32] = make_uint4(L[0],L[1],L[2],L[3]);
    }
  } else {
    const float* W = Ws[b-1];
    for (int idx = threadIdx.x; idx < 8*8*32; idx += 256){
      int lane = idx & 31, k = (idx >> 5) & 7, band = idx >> 8;
      u32 H[4], L[4];
      #pragma unroll
      for (int j = 0; j < 4; j++){
        int row = band*16 + (lane>>2) + (j&1)*8;
        int cd  = k*16 + (lane&3)*2 + (j>>1)*8;
        float p = W[cd*128 + row];
        float q = W[(cd+1)*128 + row];
        H[j] = h2pack(p,q);
        L[j] = h2lo(p,q,H[j]);
      }
      int base = ((((b-1)*8 + band)*8 + k)*2)*32 + lane;
      g_wf[base]      = make_uint4(H[0],H[1],H[2],H[3]);
      g_wf[base + 32] = make_uint4(L[0],L[1],L[2],L[3]);
    }
  }
}

// ---------------- main kernel: one graph per 256-thread CTA, 3 CTAs/SM ----------------
__global__ void __launch_bounds__(NT, 3)
net_kernel(const float* __restrict__ lm,
           const float* __restrict__ Wr, const float* __restrict__ br,
           const float* __restrict__ b0, const float* __restrict__ b1,
           const float* __restrict__ b2, const float* __restrict__ b3,
           const float* __restrict__ gamma, const float* __restrict__ beta,
           float* __restrict__ out)
{
  extern __shared__ char st[];
  const int tid  = threadIdx.x;
  const int wl   = tid >> 5;            // warp 0..7
  const int lane = tid & 31;
  const int gg   = blockIdx.x;          // graph id

  float* sG  = (float*)(st + O_G);
  float* sBe = (float*)(st + O_BE);
  float* sS  = (float*)(st + O_SS);
  float* sSw = (float*)(st + O_SW);
  float* xnat  = (float*)st;            // init fp32 scratch (aliases xT hi+lo span)
  float* xnat2 = (float*)st;            // final fp32 out (aliases xT span; xT dead at L==3 epi)

  const u32 sb   = (u32)__cvta_generic_to_shared(st);
  const u32 xh_b = sb + XH_OF;
  const u32 ah_b = sb + AH_OF;

  const int rsel = lane & 15;
  const int csel = (lane >> 4) << 3;
  const int r0   = lane >> 2;
  const int cc   = (lane & 3) * 2;

  const float* Bs[4] = {b0, b1, b2, b3};

  // ================= init =================
  {
    const float4* src = (const float4*)(lm + (size_t)gg * (LMN*128));
    for (int i = tid; i < LMN*32; i += NT){
      int row = i >> 5, c4 = i & 31;
      ((float4*)(xnat + row*132))[c4] = src[i];
    }
  }
  if (tid < 128){ sG[tid] = gamma[tid]; sBe[tid] = beta[tid]; }
  __syncthreads();

  // region-pool scores
  {
    const float brv = __ldg(br);
    const float4 wv = __ldg((const float4*)Wr + lane);
    for (int n = wl; n < LMN; n += 8){
      float4 xv = ((const float4*)(xnat + n*132))[lane];
      float d = xv.x*wv.x + xv.y*wv.y + xv.z*wv.z + xv.w*wv.w;
      #pragma unroll
      for (int o = 16; o; o >>= 1) d += __shfl_xor_sync(0xffffffffu, d, o);
      if (lane == 0) sS[n] = d + brv;
    }
  }
  __syncthreads();
  if (tid < 9){
    int2 re = c_reg[tid];
    float mx = -3.4e38f;
    for (int n = re.x; n <= re.y; n++) mx = fmaxf(mx, sS[n]);
    float sum = 0.f;
    for (int n = re.x; n <= re.y; n++){ float e = expf(sS[n]-mx); sSw[n] = e; sum += e; }
    float inv = 1.f/sum;
    for (int n = re.x; n <= re.y; n++) sSw[n] *= inv;
  }
  __syncthreads();
  for (int i = tid; i < 9*128; i += NT){
    int r = i >> 7, d = i & 127;
    int2 re = c_reg[r];
    float acc = 0.f;
    for (int n = re.x; n <= re.y; n++) acc = fmaf(sSw[n], xnat[n*132 + d], acc);
    xnat[(LMN + r)*132 + d] = acc;
  }
  __syncthreads();

  // build initial xT[d=128][n<80] fp16 hi/lo (read-all-to-regs, then overwrite alias)
  {
    const int d  = tid >> 1;
    const int n0 = (tid & 1) * 40;
    float v[40];
    #pragma unroll
    for (int j = 0; j < 40; j++){
      int n = n0 + j;
      v[j] = (n < NTOT) ? xnat[n*132 + d] : 0.f;
    }
    __syncthreads();   // all reads done before writing over the alias
    #pragma unroll
    for (int c = 0; c < 5; c++){
      u32 H[4], L[4];
      #pragma unroll
      for (int p = 0; p < 4; p++){
        float a = v[c*8 + p*2], b = v[c*8 + p*2 + 1];
        H[p] = h2pack(a,b);
        L[p] = h2lo(a,b,H[p]);
      }
      u32 off = (u32)(d*XSTRB + (n0 + c*8)*2);
      *(uint4*)(st + XH_OF + off) = make_uint4(H[0],H[1],H[2],H[3]);
      *(uint4*)(st + XL_OF + off) = make_uint4(L[0],L[1],L[2],L[3]);
    }
  }
  __syncthreads();

  // ================= layer loop =================
  #pragma unroll 1
  for (int L = 0; L < 4; L++){
    // ---------- GEMM1: agg[n<80][d] = adj @ x ; warp tile 80n x 16d, K=80 ----------
    // A = adj fp16 hi/lo (global frags, loaded in-loop), B = xT hi tile only
    {
      const int nc = wl * 16;          // warp-private d-stripe
      float acc[40];
      #pragma unroll
      for (int q = 0; q < 40; q++) acc[q] = 0.f;
      #pragma unroll
      for (int k = 0; k < 5; k++){
        const int kc = k*16 + csel;
        u32 bh[4];
        ldm4(bh, xh_b + (u32)((nc + rsel)*XSTRB + kc*2));
        #pragma unroll
        for (int b = 0; b < 5; b++){
          uint4 aH = g_af[((b*5 + k)*2    )*32 + lane];
          uint4 aL = g_af[((b*5 + k)*2 + 1)*32 + lane];
          #pragma unroll
          for (int j = 0; j < 2; j++){
            float* c = acc + (b*2 + j)*4;
            mma(c, (const u32*)&aH, bh[j], bh[2+j]);
            mma(c, (const u32*)&aL, bh[j], bh[2+j]);
          }
        }
      }
      // store -> agg hi (single fp16 tile; disjoint region)
      #pragma unroll
      for (int b = 0; b < 5; b++)
        #pragma unroll
        for (int j = 0; j < 2; j++)
          #pragma unroll
          for (int h = 0; h < 2; h++){
            float pp = acc[(b*2+j)*4 + h*2], qq = acc[(b*2+j)*4 + h*2 + 1];
            u32 off = (u32)((b*16 + r0 + h*8)*ASTRB + (nc + j*8 + cc)*2);
            *(u32*)(st + AH_OF + off) = h2pack(pp,qq);
          }
    }
    __syncthreads();

    // ---------- GEMM2: outT[o][n] = W^T @ agg^T ; warp tile 32o x 40n, K=128 ----------
    // A = W fp16 hi/lo (global frags, loaded in-loop; L1-hot), B = agg hi only
    {
      const int mr = (wl >> 1) * 32;   // o-stripe
      const int nb = (wl & 1) * 40;    // n-half
      const int band0 = (wl >> 1) * 2;
      const uint4* wf0 = g_wf + (((L*8 + band0    )*8)*2)*32 + lane;
      const uint4* wf1 = g_wf + (((L*8 + band0 + 1)*8)*2)*32 + lane;
      float acc[40];
      #pragma unroll
      for (int q = 0; q < 40; q++) acc[q] = 0.f;
      #pragma unroll
      for (int k = 0; k < 8; k++){
        const int kc = k*16 + csel;
        u32 bh01[4], bh23[4], bh4[4];
        {
          u32 rb = ah_b + (u32)((nb + rsel)*ASTRB + kc*2);
          ldm4(bh01, rb);
          ldm4(bh23, rb + 16*ASTRB);
          // last band has only 8 valid rows (nb+32..nb+39): clamp row-select so all
          // sub-matrices stay in-bounds; matrices 1/3 are duplicates and unused.
          u32 rb4 = ah_b + (u32)((nb + 32 + (rsel & 7))*ASTRB + kc*2);
          ldm4(bh4, rb4);
        }
        u32 B0h[5] = {bh01[0], bh01[1], bh23[0], bh23[1], bh4[0]};
        u32 B1h[5] = {bh01[2], bh01[3], bh23[2], bh23[3], bh4[2]};
        #pragma unroll
        for (int sb2 = 0; sb2 < 2; sb2++){
          const uint4* wf = sb2 ? wf1 : wf0;
          uint4 aH = wf[k*64];
          uint4 aL = wf[k*64 + 32];
          #pragma unroll
          for (int j = 0; j < 5; j++){
            float* c = acc + (sb2*5 + j)*4;
            mma(c, (const u32*)&aH, B0h[j], B1h[j]);
            mma(c, (const u32*)&aL, B0h[j], B1h[j]);
          }
        }
      }
      // epilogue
      if (L == 3) __syncthreads();   // all tile reads settled before alias overwrite
      #pragma unroll
      for (int sb2 = 0; sb2 < 2; sb2++){
        const float bias0 = __ldg(Bs[L] + mr + sb2*16 + r0);
        const float bias1 = __ldg(Bs[L] + mr + sb2*16 + r0 + 8);
        #pragma unroll
        for (int j = 0; j < 5; j++){
          const float* c = acc + (sb2*5 + j)*4;
          #pragma unroll
          for (int h = 0; h < 2; h++){
            const float bia = h ? bias1 : bias0;
            float f0 = fmaxf(c[h*2]     + bia, 0.f);
            float f1 = fmaxf(c[h*2 + 1] + bia, 0.f);
            const int row = mr + sb2*16 + r0 + h*8;
            const int col = nb + j*8 + cc;
            if (L < 3){
              u32 off = (u32)(row*XSTRB + col*2);
              float2 h2 = h2unpack(*(u32*)(st + XH_OF + off));
              float2 l2 = h2unpack(*(u32*)(st + XL_OF + off));
              f0 += h2.x + l2.x;
              f1 += h2.y + l2.y;
              u32 nh2 = h2pack(f0,f1);
              *(u32*)(st + XH_OF + off) = nh2;
              *(u32*)(st + XL_OF + off) = h2lo(f0,f1,nh2);
            } else {
              if (col   < NTOT) xnat2[col*132 + row]     = f0;
              if (col+1 < NTOT) xnat2[(col+1)*132 + row] = f1;
            }
          }
        }
      }
    }
    __syncthreads();
  }

  // ================= LayerNorm + writeout =================
  {
    const float4 gv  = ((const float4*)sG)[lane];
    const float4 bev = ((const float4*)sBe)[lane];
    for (int n = wl; n < NTOT; n += 8){
      float4 v = *(const float4*)(xnat2 + n*132 + lane*4);
      float s  = v.x + v.y + v.z + v.w;
      float s2 = v.x*v.x + v.y*v.y + v.z*v.z + v.w*v.w;
      #pragma unroll
      for (int o = 16; o; o >>= 1){
        s  += __shfl_xor_sync(0xffffffffu, s,  o);
        s2 += __shfl_xor_sync(0xffffffffu, s2, o);
      }
      float mu  = s * (1.f/128.f);
      float var = s2 * (1.f/128.f) - mu*mu;
      float inv = rsqrtf(var + 1e-5f);
      float4 o4;
      o4.x = (v.x - mu)*inv*gv.x + bev.x;
      o4.y = (v.y - mu)*inv*gv.y + bev.y;
      o4.z = (v.z - mu)*inv*gv.z + bev.z;
      o4.w = (v.w - mu)*inv*gv.w + bev.w;
      ((float4*)(out + ((size_t)gg*NTOT + n)*128))[lane] = o4;
    }
  }
}

extern "C" void kernel_launch(void* const* d_in, const int* in_sizes, int n_in,
                              void* d_out, int out_size)
{
  const float* lm    = (const float*)d_in[0];
  const float* adj   = (const float*)d_in[1];
  const float* Wr    = (const float*)d_in[2];
  const float* br    = (const float*)d_in[3];
  const float* W0    = (const float*)d_in[4];
  const float* b0    = (const float*)d_in[5];
  const float* W1    = (const float*)d_in[6];
  const float* b1    = (const float*)d_in[7];
  const float* W2    = (const float*)d_in[8];
  const float* b2    = (const float*)d_in[9];
  const float* W3    = (const float*)d_in[10];
  const float* b3    = (const float*)d_in[11];
  const float* gamma = (const float*)d_in[12];
  const float* beta  = (const float*)d_in[13];
  float* out = (float*)d_out;

  format_kernel<<<5, 256>>>(adj, W0, W1, W2, W3);
  cudaFuncSetAttribute(net_kernel, cudaFuncAttributeMaxDynamicSharedMemorySize, SMEM_SZ);
  net_kernel<<<4096, NT, SMEM_SZ>>>(lm, Wr, br, b0, b1, b2, b3, gamma, beta, out);
}

// round 15
// speedup vs baseline: 1.3502x; 1.3502x over previous
#include <cuda_runtime.h>
#include <cuda_fp16.h>
#include <cstdint>

typedef uint32_t u32;

#define NT     256
#define LMN    68
#define NTOT   77
#define XSTRB  176        // xT row bytes (80 n-cols padded, fp16)
#define ASTRB  272        // agg row bytes (128 d-cols padded, fp16)

// state block (per CTA = one graph)
#define XH_OF  0          // xT hi tile  (128 x 176B = 22528)
#define AH_OF  22528      // agg tile    (80 x 272B = 21760)
#define GSZ    44288
#define O_G    (GSZ)
#define O_BE   (GSZ+512)
#define O_SS   (GSZ+1024)
#define O_SW   (GSZ+1408)
#define SMEM_SZ (GSZ+1792)   // 46080 B

// frag tables: exact mma.m16n8k16 A-fragment layout, single fp16
__device__ uint4 g_af[5*5*32];        // adj  [band5][k5][lane32]
__device__ uint4 g_wf[4*8*8*32];      // W^T  [L4][band8][k8][lane32]

__constant__ int2 c_reg[9] = {
  {0,16},{17,21},{22,26},{27,30},{31,35},{36,41},{42,47},{48,59},{60,67}
};

__device__ __forceinline__ u32 h2pack(float a, float b){ // low16=fp16(a), high16=fp16(b)
  __half2 h = __floats2half2_rn(a, b);
  return *(u32*)&h;
}
__device__ __forceinline__ void ldm4(u32* r, u32 addr){
  asm volatile("ldmatrix.sync.aligned.m8n8.x4.shared.b16 {%0,%1,%2,%3}, [%4];"
    : "=r"(r[0]),"=r"(r[1]),"=r"(r[2]),"=r"(r[3]) : "r"(addr));
}
__device__ __forceinline__ void mma(float* c, const u32* a, u32 b0, u32 b1){
  asm volatile("mma.sync.aligned.m16n8k16.row.col.f32.f16.f16.f32 "
    "{%0,%1,%2,%3},{%4,%5,%6,%7},{%8,%9},{%0,%1,%2,%3};"
    : "+f"(c[0]),"+f"(c[1]),"+f"(c[2]),"+f"(c[3])
    : "r"(a[0]),"r"(a[1]),"r"(a[2]),"r"(a[3]), "r"(b0),"r"(b1));
}

// ---------------- format kernel: build fp16 A-frag tables ----------------
__global__ void __launch_bounds__(256)
format_kernel(const float* __restrict__ adj,
              const float* __restrict__ W0, const float* __restrict__ W1,
              const float* __restrict__ W2, const float* __restrict__ W3)
{
  const int b = blockIdx.x;
  const float* Ws[4] = {W0,W1,W2,W3};
  if (b == 0){
    for (int idx = threadIdx.x; idx < 5*5*32; idx += 256){
      int lane = idx & 31, k = (idx >> 5) % 5, band = idx / 160;
      u32 H[4];
      #pragma unroll
      for (int j = 0; j < 4; j++){
        int row = band*16 + (lane>>2) + (j&1)*8;
        int cp  = k*16 + (lane&3)*2 + (j>>1)*8;
        float p = (row < NTOT && cp   < NTOT) ? adj[row*NTOT + cp]   : 0.f;
        float q = (row < NTOT && cp+1 < NTOT) ? adj[row*NTOT + cp+1] : 0.f;
        H[j] = h2pack(p,q);
      }
      g_af[(band*5 + k)*32 + lane] = make_uint4(H[0],H[1],H[2],H[3]);
    }
  } else {
    const float* W = Ws[b-1];
    for (int idx = threadIdx.x; idx < 8*8*32; idx += 256){
      int lane = idx & 31, k = (idx >> 5) & 7, band = idx >> 8;
      u32 H[4];
      #pragma unroll
      for (int j = 0; j < 4; j++){
        int row = band*16 + (lane>>2) + (j&1)*8;
        int cd  = k*16 + (lane&3)*2 + (j>>1)*8;
        H[j] = h2pack(W[cd*128 + row], W[(cd+1)*128 + row]);
      }
      g_wf[(((b-1)*8 + band)*8 + k)*32 + lane] = make_uint4(H[0],H[1],H[2],H[3]);
    }
  }
}

// ---------------- main kernel: one graph per 256-thread CTA, 2 CTAs/SM ----------------
__global__ void __launch_bounds__(NT, 2)
net_kernel(const float* __restrict__ lm,
           const float* __restrict__ Wr, const float* __restrict__ br,
           const float* __restrict__ b0, const float* __restrict__ b1,
           const float* __restrict__ b2, const float* __restrict__ b3,
           const float* __restrict__ gamma, const float* __restrict__ beta,
           float* __restrict__ out)
{
  extern __shared__ char st[];
  const int tid  = threadIdx.x;
  const int wl   = tid >> 5;            // warp 0..7
  const int lane = tid & 31;
  const int gg   = blockIdx.x;          // graph id

  float* sG  = (float*)(st + O_G);
  float* sBe = (float*)(st + O_BE);
  float* sS  = (float*)(st + O_SS);
  float* sSw = (float*)(st + O_SW);
  float* xnat  = (float*)st;            // init fp32 scratch (aliases XH+AH span, 42240<=44288)
  float* xnat2 = (float*)st;            // final fp32 out (same alias; tiles dead at L==3 epi)

  const u32 sb   = (u32)__cvta_generic_to_shared(st);
  const u32 xh_b = sb + XH_OF;
  const u32 ah_b = sb + AH_OF;

  const int rsel = lane & 15;
  const int csel = (lane >> 4) << 3;
  const int r0   = lane >> 2;
  const int cc   = (lane & 3) * 2;

  // GEMM2 / residual warp-tile coordinates (fixed ownership across layers)
  const int mr = (wl >> 1) * 32;   // o / d stripe
  const int nb = (wl & 1) * 40;    // n half

  const float* Bs[4] = {b0, b1, b2, b3};

  // ================= init =================
  {
    const float4* src = (const float4*)(lm + (size_t)gg * (LMN*128));
    for (int i = tid; i < LMN*32; i += NT){
      int row = i >> 5, c4 = i & 31;
      ((float4*)(xnat + row*132))[c4] = src[i];
    }
  }
  if (tid < 128){ sG[tid] = gamma[tid]; sBe[tid] = beta[tid]; }
  __syncthreads();

  // region-pool scores
  {
    const float brv = __ldg(br);
    const float4 wv = __ldg((const float4*)Wr + lane);
    for (int n = wl; n < LMN; n += 8){
      float4 xv = ((const float4*)(xnat + n*132))[lane];
      float d = xv.x*wv.x + xv.y*wv.y + xv.z*wv.z + xv.w*wv.w;
      #pragma unroll
      for (int o = 16; o; o >>= 1) d += __shfl_xor_sync(0xffffffffu, d, o);
      if (lane == 0) sS[n] = d + brv;
    }
  }
  __syncthreads();
  if (tid < 9){
    int2 re = c_reg[tid];
    float mx = -3.4e38f;
    for (int n = re.x; n <= re.y; n++) mx = fmaxf(mx, sS[n]);
    float sum = 0.f;
    for (int n = re.x; n <= re.y; n++){ float e = expf(sS[n]-mx); sSw[n] = e; sum += e; }
    float inv = 1.f/sum;
    for (int n = re.x; n <= re.y; n++) sSw[n] *= inv;
  }
  __syncthreads();
  for (int i = tid; i < 9*128; i += NT){
    int r = i >> 7, d = i & 127;
    int2 re = c_reg[r];
    float acc = 0.f;
    for (int n = re.x; n <= re.y; n++) acc = fmaf(sSw[n], xnat[n*132 + d], acc);
    xnat[(LMN + r)*132 + d] = acc;
  }
  __syncthreads();

  // ---- residual init (register-resident, GEMM2 C-frag shaped, fp32 exact) ----
  float resid[40];
  #pragma unroll
  for (int sb2 = 0; sb2 < 2; sb2++)
    #pragma unroll
    for (int j = 0; j < 5; j++)
      #pragma unroll
      for (int h = 0; h < 2; h++)
        #pragma unroll
        for (int e = 0; e < 2; e++){
          int row = mr + sb2*16 + r0 + h*8;
          int col = nb + j*8 + cc + e;
          resid[(sb2*5+j)*4 + h*2 + e] = (col < NTOT) ? xnat[col*132 + row] : 0.f;
        }

  // ---- build initial xT[d=128][n<80] fp16 (read-all-to-regs, then overwrite alias) ----
  {
    const int d  = tid >> 1;
    const int n0 = (tid & 1) * 40;
    float v[40];
    #pragma unroll
    for (int j = 0; j < 40; j++){
      int n = n0 + j;
      v[j] = (n < NTOT) ? xnat[n*132 + d] : 0.f;
    }
    __syncthreads();   // all xnat reads done before writing over the alias
    #pragma unroll
    for (int c = 0; c < 5; c++){
      u32 H[4];
      #pragma unroll
      for (int p = 0; p < 4; p++)
        H[p] = h2pack(v[c*8 + p*2], v[c*8 + p*2 + 1]);
      u32 off = (u32)(d*XSTRB + (n0 + c*8)*2);
      *(uint4*)(st + XH_OF + off) = make_uint4(H[0],H[1],H[2],H[3]);
    }
  }
  __syncthreads();

  // ================= layer loop =================
  #pragma unroll 1
  for (int L = 0; L < 4; L++){
    // ---------- GEMM1: agg[n<80][d] = adj @ x ; warp tile 80n x 16d, K=80 ----------
    // A = adj fp16 (global frags), B = xT fp16
    {
      const int nc = wl * 16;          // warp-private d-stripe
      float acc[40];
      #pragma unroll
      for (int q = 0; q < 40; q++) acc[q] = 0.f;
      #pragma unroll
      for (int k = 0; k < 5; k++){
        const int kc = k*16 + csel;
        u32 bh[4];
        ldm4(bh, xh_b + (u32)((nc + rsel)*XSTRB + kc*2));
        #pragma unroll
        for (int b = 0; b < 5; b++){
          uint4 aH = g_af[(b*5 + k)*32 + lane];
          #pragma unroll
          for (int j = 0; j < 2; j++)
            mma(acc + (b*2 + j)*4, (const u32*)&aH, bh[j], bh[2+j]);
        }
      }
      // store -> agg (single fp16 tile; disjoint region)
      #pragma unroll
      for (int b = 0; b < 5; b++)
        #pragma unroll
        for (int j = 0; j < 2; j++)
          #pragma unroll
          for (int h = 0; h < 2; h++){
            float pp = acc[(b*2+j)*4 + h*2], qq = acc[(b*2+j)*4 + h*2 + 1];
            u32 off = (u32)((b*16 + r0 + h*8)*ASTRB + (nc + j*8 + cc)*2);
            *(u32*)(st + AH_OF + off) = h2pack(pp,qq);
          }
    }
    __syncthreads();

    // ---------- GEMM2: outT[o][n] = W^T @ agg^T ; warp tile 32o x 40n, K=128 ----------
    // A = W fp16 (global frags, L1-hot), B = agg fp16
    {
      const int band0 = (wl >> 1) * 2;
      float acc[40];
      #pragma unroll
      for (int q = 0; q < 40; q++) acc[q] = 0.f;
      #pragma unroll
      for (int k = 0; k < 8; k++){
        const int kc = k*16 + csel;
        u32 bh01[4], bh23[4], bh4[4];
        {
          u32 rb = ah_b + (u32)((nb + rsel)*ASTRB + kc*2);
          ldm4(bh01, rb);
          ldm4(bh23, rb + 16*ASTRB);
          // last band has only 8 valid rows (nb+32..nb+39): clamp row-select so all
          // sub-matrices stay in-bounds; matrices 1/3 are duplicates and unused.
          u32 rb4 = ah_b + (u32)((nb + 32 + (rsel & 7))*ASTRB + kc*2);
          ldm4(bh4, rb4);
        }
        u32 B0h[5] = {bh01[0], bh01[1], bh23[0], bh23[1], bh4[0]};
        u32 B1h[5] = {bh01[2], bh01[3], bh23[2], bh23[3], bh4[2]};
        #pragma unroll
        for (int sb2 = 0; sb2 < 2; sb2++){
          uint4 aH = g_wf[((L*8 + band0 + sb2)*8 + k)*32 + lane];
          #pragma unroll
          for (int j = 0; j < 5; j++)
            mma(acc + (sb2*5 + j)*4, (const u32*)&aH, B0h[j], B1h[j]);
        }
      }
      // epilogue: bias + relu (+ residual from regs)
      if (L == 3) __syncthreads();   // all tile reads settled before alias overwrite
      #pragma unroll
      for (int sb2 = 0; sb2 < 2; sb2++){
        const float bias0 = __ldg(Bs[L] + mr + sb2*16 + r0);
        const float bias1 = __ldg(Bs[L] + mr + sb2*16 + r0 + 8);
        #pragma unroll
        for (int j = 0; j < 5; j++){
          float* c = acc + (sb2*5 + j)*4;
          #pragma unroll
          for (int h = 0; h < 2; h++){
            const float bia = h ? bias1 : bias0;
            const int idx = (sb2*5+j)*4 + h*2;
            const int row = mr + sb2*16 + r0 + h*8;
            const int col = nb + j*8 + cc;
            if (L < 3){
              float f0 = fmaxf(c[h*2]     + bia, 0.f) + resid[idx];
              float f1 = fmaxf(c[h*2 + 1] + bia, 0.f) + resid[idx+1];
              resid[idx]   = f0;
              resid[idx+1] = f1;
              *(u32*)(st + XH_OF + (u32)(row*XSTRB + col*2)) = h2pack(f0,f1);
            } else {
              float f0 = fmaxf(c[h*2]     + bia, 0.f);
              float f1 = fmaxf(c[h*2 + 1] + bia, 0.f);
              if (col   < NTOT) xnat2[col*132 + row]     = f0;
              if (col+1 < NTOT) xnat2[(col+1)*132 + row] = f1;
            }
          }
        }
      }
    }
    __syncthreads();
  }

  // ================= LayerNorm + writeout =================
  {
    const float4 gv  = ((const float4*)sG)[lane];
    const float4 bev = ((const float4*)sBe)[lane];
    for (int n = wl; n < NTOT; n += 8){
      float4 v = *(const float4*)(xnat2 + n*132 + lane*4);
      float s  = v.x + v.y + v.z + v.w;
      float s2 = v.x*v.x + v.y*v.y + v.z*v.z + v.w*v.w;
      #pragma unroll
      for (int o = 16; o; o >>= 1){
        s  += __shfl_xor_sync(0xffffffffu, s,  o);
        s2 += __shfl_xor_sync(0xffffffffu, s2, o);
      }
      float mu  = s * (1.f/128.f);
      float var = s2 * (1.f/128.f) - mu*mu;
      float inv = rsqrtf(var + 1e-5f);
      float4 o4;
      o4.x = (v.x - mu)*inv*gv.x + bev.x;
      o4.y = (v.y - mu)*inv*gv.y + bev.y;
      o4.z = (v.z - mu)*inv*gv.z + bev.z;
      o4.w = (v.w - mu)*inv*gv.w + bev.w;
      ((float4*)(out + ((size_t)gg*NTOT + n)*128))[lane] = o4;
    }
  }
}

extern "C" void kernel_launch(void* const* d_in, const int* in_sizes, int n_in,
                              void* d_out, int out_size)
{
  const float* lm    = (const float*)d_in[0];
  const float* adj   = (const float*)d_in[1];
  const float* Wr    = (const float*)d_in[2];
  const float* br    = (const float*)d_in[3];
  const float* W0    = (const float*)d_in[4];
  const float* b0    = (const float*)d_in[5];
  const float* W1    = (const float*)d_in[6];
  const float* b1    = (const float*)d_in[7];
  const float* W2    = (const float*)d_in[8];
  const float* b2    = (const float*)d_in[9];
  const float* W3    = (const float*)d_in[10];
  const float* b3    = (const float*)d_in[11];
  const float* gamma = (const float*)d_in[12];
  const float* beta  = (const float*)d_in[13];
  float* out = (float*)d_out;

  format_kernel<<<5, 256>>>(adj, W0, W1, W2, W3);
  cudaFuncSetAttribute(net_kernel, cudaFuncAttributeMaxDynamicSharedMemorySize, SMEM_SZ);
  net_kernel<<<4096, NT, SMEM_SZ>>>(lm, Wr, br, b0, b1, b2, b3, gamma, beta, out);
}

// round 16
// speedup vs baseline: 1.4605x; 1.0817x over previous
#include <cuda_runtime.h>
#include <cuda_fp16.h>
#include <cstdint>

typedef uint32_t u32;

#define NT     256
#define LMN    68
#define NTOT   77
#define XNSTR  272        // x  row bytes: [node 80][d 128] fp16 padded
#define YSTR   176        // Y  row bytes: [o 128][m 80] fp16 padded

// state block (per CTA = one graph)
#define XN_OF  0          // x tile (80 x 272B = 21760)
#define Y_OF   21760      // Y tile (128 x 176B = 22528)
#define GSZ    44288
#define O_G    (GSZ)
#define O_BE   (GSZ+512)
#define O_SS   (GSZ+1024)
#define O_SW   (GSZ+1408)
#define SMEM_SZ (GSZ+1792)   // 46080 B -> 2 CTAs/SM

// static operand tables (single fp16):
//   g_wf: W^T A-frags  (mma A layout)  [L4][o-band8][k=d 8][lane32] uint4
//   g_bf: adj^T B-frags (mma B layout) [k=m band5][n-blk10][lane32] uint2
__device__ uint4 g_wf[4*8*8*32];
__device__ uint2 g_bf[5*10*32];

__constant__ int2 c_reg[9] = {
  {0,16},{17,21},{22,26},{27,30},{31,35},{36,41},{42,47},{48,59},{60,67}
};

__device__ __forceinline__ u32 h2pack(float a, float b){ // low16=fp16(a), high16=fp16(b)
  __half2 h = __floats2half2_rn(a, b);
  return *(u32*)&h;
}
__device__ __forceinline__ void ldm4(u32* r, u32 addr){
  asm volatile("ldmatrix.sync.aligned.m8n8.x4.shared.b16 {%0,%1,%2,%3}, [%4];"
    : "=r"(r[0]),"=r"(r[1]),"=r"(r[2]),"=r"(r[3]) : "r"(addr));
}
__device__ __forceinline__ void ldm2(u32* r, u32 addr){
  asm volatile("ldmatrix.sync.aligned.m8n8.x2.shared.b16 {%0,%1}, [%2];"
    : "=r"(r[0]),"=r"(r[1]) : "r"(addr));
}
__device__ __forceinline__ void mma(float* c, const u32* a, u32 b0, u32 b1){
  asm volatile("mma.sync.aligned.m16n8k16.row.col.f32.f16.f16.f32 "
    "{%0,%1,%2,%3},{%4,%5,%6,%7},{%8,%9},{%0,%1,%2,%3};"
    : "+f"(c[0]),"+f"(c[1]),"+f"(c[2]),"+f"(c[3])
    : "r"(a[0]),"r"(a[1]),"r"(a[2]),"r"(a[3]), "r"(b0),"r"(b1));
}

// ---------------- format kernel: build static frag tables ----------------
__global__ void __launch_bounds__(256)
format_kernel(const float* __restrict__ adj,
              const float* __restrict__ W0, const float* __restrict__ W1,
              const float* __restrict__ W2, const float* __restrict__ W3)
{
  const int b = blockIdx.x;
  const float* Ws[4] = {W0,W1,W2,W3};
  if (b == 0){
    // adj^T B-frags: frag (kb: m-band of 16, j: n-block of 8)
    // lane l: n = j*8 + (l>>2); b0 = adjT[kb*16+(l&3)*2 +0,1][n]; b1 = +8,+9
    // adjT[m][n] = adj[n][m]; zero-pad m,n >= 77
    for (int idx = threadIdx.x; idx < 5*10*32; idx += 256){
      int lane = idx & 31, j = (idx >> 5) % 10, kb = idx / 320;
      int n  = j*8 + (lane>>2);
      int m0 = kb*16 + (lane&3)*2;
      float p0=0.f,q0=0.f,p1=0.f,q1=0.f;
      if (n < NTOT){
        if (m0   < NTOT) p0 = adj[n*NTOT + m0];
        if (m0+1 < NTOT) q0 = adj[n*NTOT + m0+1];
        if (m0+8 < NTOT) p1 = adj[n*NTOT + m0+8];
        if (m0+9 < NTOT) q1 = adj[n*NTOT + m0+9];
      }
      g_bf[(kb*10 + j)*32 + lane] = make_uint2(h2pack(p0,q0), h2pack(p1,q1));
    }
  } else {
    // W^T A-frags (row-major 16o x 16d), k = d
    const float* W = Ws[b-1];
    for (int idx = threadIdx.x; idx < 8*8*32; idx += 256){
      int lane = idx & 31, k = (idx >> 5) & 7, band = idx >> 8;
      u32 H[4];
      #pragma unroll
      for (int j = 0; j < 4; j++){
        int row = band*16 + (lane>>2) + (j&1)*8;   // o
        int cd  = k*16 + (lane&3)*2 + (j>>1)*8;    // d
        H[j] = h2pack(W[cd*128 + row], W[(cd+1)*128 + row]);
      }
      g_wf[(((b-1)*8 + band)*8 + k)*32 + lane] = make_uint4(H[0],H[1],H[2],H[3]);
    }
  }
}

// ---------------- main kernel: one graph per 256-thread CTA, 2 CTAs/SM ----------------
__global__ void __launch_bounds__(NT, 2)
net_kernel(const float* __restrict__ lm,
           const float* __restrict__ Wr, const float* __restrict__ br,
           const float* __restrict__ b0, const float* __restrict__ b1,
           const float* __restrict__ b2, const float* __restrict__ b3,
           const float* __restrict__ gamma, const float* __restrict__ beta,
           float* __restrict__ out)
{
  extern __shared__ char st[];
  const int tid  = threadIdx.x;
  const int wl   = tid >> 5;            // warp 0..7
  const int lane = tid & 31;
  const int gg   = blockIdx.x;          // graph id

  float* sG  = (float*)(st + O_G);
  float* sBe = (float*)(st + O_BE);
  float* sS  = (float*)(st + O_SS);
  float* sSw = (float*)(st + O_SW);
  float* xnat  = (float*)st;            // init fp32 scratch (aliases XN+Y span, 42240<=44288)
  float* xnat2 = (float*)st;            // final fp32 out (same alias; tiles dead at L==3 epi)

  const u32 sb   = (u32)__cvta_generic_to_shared(st);
  const u32 xn_b = sb + XN_OF;
  const u32 y_b  = sb + Y_OF;

  const int rsel = lane & 15;
  const int csel = (lane >> 4) << 3;
  const int r0   = lane >> 2;
  const int cc   = (lane & 3) * 2;

  // warp-tile coordinates (fixed ownership across layers, both GEMMs + residual)
  const int mr = (wl >> 1) * 32;   // o stripe
  const int nb = (wl & 1) * 40;    // m half (stage1) / n half (stage2)

  const float* Bs[4] = {b0, b1, b2, b3};

  // ================= init =================
  {
    const float4* src = (const float4*)(lm + (size_t)gg * (LMN*128));
    for (int i = tid; i < LMN*32; i += NT){
      int row = i >> 5, c4 = i & 31;
      ((float4*)(xnat + row*132))[c4] = src[i];
    }
  }
  if (tid < 128){ sG[tid] = gamma[tid]; sBe[tid] = beta[tid]; }
  __syncthreads();

  // region-pool scores
  {
    const float brv = __ldg(br);
    const float4 wv = __ldg((const float4*)Wr + lane);
    for (int n = wl; n < LMN; n += 8){
      float4 xv = ((const float4*)(xnat + n*132))[lane];
      float d = xv.x*wv.x + xv.y*wv.y + xv.z*wv.z + xv.w*wv.w;
      #pragma unroll
      for (int o = 16; o; o >>= 1) d += __shfl_xor_sync(0xffffffffu, d, o);
      if (lane == 0) sS[n] = d + brv;
    }
  }
  __syncthreads();
  if (tid < 9){
    int2 re = c_reg[tid];
    float mx = -3.4e38f;
    for (int n = re.x; n <= re.y; n++) mx = fmaxf(mx, sS[n]);
    float sum = 0.f;
    for (int n = re.x; n <= re.y; n++){ float e = expf(sS[n]-mx); sSw[n] = e; sum += e; }
    float inv = 1.f/sum;
    for (int n = re.x; n <= re.y; n++) sSw[n] *= inv;
  }
  __syncthreads();
  for (int i = tid; i < 9*128; i += NT){
    int r = i >> 7, d = i & 127;
    int2 re = c_reg[r];
    float acc = 0.f;
    for (int n = re.x; n <= re.y; n++) acc = fmaf(sSw[n], xnat[n*132 + d], acc);
    xnat[(LMN + r)*132 + d] = acc;
  }
  __syncthreads();

  // ---- residual init (register-resident, stage2 C-frag shaped, fp32 exact) ----
  float resid[40];
  #pragma unroll
  for (int sb2 = 0; sb2 < 2; sb2++)
    #pragma unroll
    for (int j = 0; j < 5; j++)
      #pragma unroll
      for (int h = 0; h < 2; h++)
        #pragma unroll
        for (int e = 0; e < 2; e++){
          int row = mr + sb2*16 + r0 + h*8;       // o / d
          int col = nb + j*8 + cc + e;            // n
          resid[(sb2*5+j)*4 + h*2 + e] = (col < NTOT) ? xnat[col*132 + row] : 0.f;
        }

  // ---- build initial x[node 80][d 128] fp16 (stage-to-regs, then overwrite alias) ----
  {
    float v[40];
    #pragma unroll
    for (int q = 0; q < 10; q++){
      int i = tid + q*NT;               // i in [0, 2560)
      int row = i >> 5, d0 = (i & 31)*4;
      #pragma unroll
      for (int e = 0; e < 4; e++)
        v[q*4+e] = (row < NTOT) ? xnat[row*132 + d0 + e] : 0.f;
    }
    __syncthreads();   // all xnat reads done before writing over the alias
    #pragma unroll
    for (int q = 0; q < 10; q++){
      int i = tid + q*NT;
      int row = i >> 5, d0 = (i & 31)*4;
      uint2 w = make_uint2(h2pack(v[q*4], v[q*4+1]), h2pack(v[q*4+2], v[q*4+3]));
      *(uint2*)(st + XN_OF + (u32)(row*XNSTR + d0*2)) = w;
    }
  }
  __syncthreads();

  // ================= layer loop =================
  #pragma unroll 1
  for (int L = 0; L < 4; L++){
    // ---------- stage1: Y[o][m] = W^T @ x^T ; warp tile 32o x 40m, K=128 ----------
    // A = W^T fp16 A-frags (global, L1-hot), B = x tile (node-major) via ldmatrix
    {
      const int band0 = (wl >> 1) * 2;
      float acc[40];
      #pragma unroll
      for (int q = 0; q < 40; q++) acc[q] = 0.f;
      #pragma unroll
      for (int k = 0; k < 8; k++){
        const int kc = k*16 + csel;
        u32 bh01[4], bh23[4], bh4[2];
        {
          u32 rb = xn_b + (u32)((nb + rsel)*XNSTR + kc*2);
          ldm4(bh01, rb);
          ldm4(bh23, rb + 16*XNSTR);
          // last 8 m-rows: x2 load (matrix0 = k lo, matrix1 = k hi)
          u32 rb4 = xn_b + (u32)((nb + 32 + (lane & 7))*XNSTR + (k*16 + ((lane >> 3) & 1)*8)*2);
          ldm2(bh4, rb4);
        }
        u32 B0[5] = {bh01[0], bh01[1], bh23[0], bh23[1], bh4[0]};
        u32 B1[5] = {bh01[2], bh01[3], bh23[2], bh23[3], bh4[1]};
        #pragma unroll
        for (int sb2 = 0; sb2 < 2; sb2++){
          uint4 aH = g_wf[((L*8 + band0 + sb2)*8 + k)*32 + lane];
          #pragma unroll
          for (int j = 0; j < 5; j++)
            mma(acc + (sb2*5 + j)*4, (const u32*)&aH, B0[j], B1[j]);
        }
      }
      // store Y (fp16, m-adjacent pairs pack into u32)
      #pragma unroll
      for (int sb2 = 0; sb2 < 2; sb2++)
        #pragma unroll
        for (int j = 0; j < 5; j++)
          #pragma unroll
          for (int h = 0; h < 2; h++){
            const float* c = acc + (sb2*5 + j)*4;
            int o = mr + sb2*16 + r0 + h*8;
            int m = nb + j*8 + cc;
            *(u32*)(st + Y_OF + (u32)(o*YSTR + m*2)) = h2pack(c[h*2], c[h*2+1]);
          }
    }
    __syncthreads();

    // ---------- stage2: outT[o][n] = Y @ adj^T ; warp tile 32o x 40n, K=80 ----------
    // A = Y (smem, ldmatrix row-major), B = adj^T fp16 B-frags (global, 256B/frag)
    {
      float acc[40];
      #pragma unroll
      for (int q = 0; q < 40; q++) acc[q] = 0.f;
      const int jb = nb >> 3;   // first n-block index
      #pragma unroll
      for (int k = 0; k < 5; k++){
        const int kc = k*16 + csel;
        u32 a0[4], a1[4];
        ldm4(a0, y_b + (u32)((mr      + rsel)*YSTR + kc*2));
        ldm4(a1, y_b + (u32)((mr + 16 + rsel)*YSTR + kc*2));
        #pragma unroll
        for (int j = 0; j < 5; j++){
          uint2 bf = g_bf[(k*10 + jb + j)*32 + lane];
          mma(acc + j*4,        a0, bf.x, bf.y);
          mma(acc + (5 + j)*4,  a1, bf.x, bf.y);
        }
      }
      // epilogue: bias + relu (+ residual from regs)
      if (L == 3) __syncthreads();   // all Y/x tile reads settled before alias overwrite
      #pragma unroll
      for (int sb2 = 0; sb2 < 2; sb2++){
        const float bias0 = __ldg(Bs[L] + mr + sb2*16 + r0);
        const float bias1 = __ldg(Bs[L] + mr + sb2*16 + r0 + 8);
        #pragma unroll
        for (int j = 0; j < 5; j++){
          float* c = acc + (sb2*5 + j)*4;
          #pragma unroll
          for (int h = 0; h < 2; h++){
            const float bia = h ? bias1 : bias0;
            const int idx = (sb2*5+j)*4 + h*2;
            const int row = mr + sb2*16 + r0 + h*8;  // o / d
            const int col = nb + j*8 + cc;           // n
            if (L < 3){
              float f0 = fmaxf(c[h*2]     + bia, 0.f) + resid[idx];
              float f1 = fmaxf(c[h*2 + 1] + bia, 0.f) + resid[idx+1];
              resid[idx]   = f0;
              resid[idx+1] = f1;
              // next x is node-major: scalar fp16 stores (adjacent n = different rows)
              *(__half*)(st + XN_OF + (u32)( col     *XNSTR + row*2)) = __float2half_rn(f0);
              *(__half*)(st + XN_OF + (u32)((col + 1)*XNSTR + row*2)) = __float2half_rn(f1);
            } else {
              float f0 = fmaxf(c[h*2]     + bia, 0.f);
              float f1 = fmaxf(c[h*2 + 1] + bia, 0.f);
              if (col   < NTOT) xnat2[col*132 + row]     = f0;
              if (col+1 < NTOT) xnat2[(col+1)*132 + row] = f1;
            }
          }
        }
      }
    }
    __syncthreads();
  }

  // ================= LayerNorm + writeout =================
  {
    const float4 gv  = ((const float4*)sG)[lane];
    const float4 bev = ((const float4*)sBe)[lane];
    for (int n = wl; n < NTOT; n += 8){
      float4 v = *(const float4*)(xnat2 + n*132 + lane*4);
      float s  = v.x + v.y + v.z + v.w;
      float s2 = v.x*v.x + v.y*v.y + v.z*v.z + v.w*v.w;
      #pragma unroll
      for (int o = 16; o; o >>= 1){
        s  += __shfl_xor_sync(0xffffffffu, s,  o);
        s2 += __shfl_xor_sync(0xffffffffu, s2, o);
      }
      float mu  = s * (1.f/128.f);
      float var = s2 * (1.f/128.f) - mu*mu;
      float inv = rsqrtf(var + 1e-5f);
      float4 o4;
      o4.x = (v.x - mu)*inv*gv.x + bev.x;
      o4.y = (v.y - mu)*inv*gv.y + bev.y;
      o4.z = (v.z - mu)*inv*gv.z + bev.z;
      o4.w = (v.w - mu)*inv*gv.w + bev.w;
      ((float4*)(out + ((size_t)gg*NTOT + n)*128))[lane] = o4;
    }
  }
}

extern "C" void kernel_launch(void* const* d_in, const int* in_sizes, int n_in,
                              void* d_out, int out_size)
{
  const float* lm    = (const float*)d_in[0];
  const float* adj   = (const float*)d_in[1];
  const float* Wr    = (const float*)d_in[2];
  const float* br    = (const float*)d_in[3];
  const float* W0    = (const float*)d_in[4];
  const float* b0    = (const float*)d_in[5];
  const float* W1    = (const float*)d_in[6];
  const float* b1    = (const float*)d_in[7];
  const float* W2    = (const float*)d_in[8];
  const float* b2    = (const float*)d_in[9];
  const float* W3    = (const float*)d_in[10];
  const float* b3    = (const float*)d_in[11];
  const float* gamma = (const float*)d_in[12];
  const float* beta  = (const float*)d_in[13];
  float* out = (float*)d_out;

  format_kernel<<<5, 256>>>(adj, W0, W1, W2, W3);
  cudaFuncSetAttribute(net_kernel, cudaFuncAttributeMaxDynamicSharedMemorySize, SMEM_SZ);
  net_kernel<<<4096, NT, SMEM_SZ>>>(lm, Wr, br, b0, b1, b2, b3, gamma, beta, out);
}